// round 1
// baseline (speedup 1.0000x reference)
#include <cuda_runtime.h>
#include <cuda_bf16.h>

// ---------------------------------------------------------------------------
// Spk_Attention: B=512, N=256, H=512
//   W_spk  = spk_emb @ W_s                       [B,N,H]
//   W_resp = true_resp @ W_r                     [B,H]
//   M      = tanh(W_spk + W_resp[:,None,:]) * mask[:,:,None]
//   s      = M . w                               [B,N]   (== mask * sum_h tanh(...)*w)
//   alpha  = softmax_N(s)
//   resp_s = sum_n alpha * spk_emb               [B,H]
//   out    = tanh(resp_s @ Wp^T + true_resp @ Wx^T)
// Outputs concatenated: resp_s [B*H] then alpha [B*N].
// ---------------------------------------------------------------------------

#define Bsz 512
#define Nn  256
#define Hh  512

// scratch (no cudaMalloc allowed)
__device__ float g_Wresp[Bsz * Hh];   // true_resp @ W_r
__device__ float g_rx[Bsz * Hh];      // true_resp @ Wx^T
__device__ float g_scores[Bsz * Nn];  // raw scores (pre-mask)
__device__ float g_resps[Bsz * Hh];   // alpha . spk_emb

// ---------------- packed f32x2 helpers (Blackwell) -------------------------
__device__ __forceinline__ unsigned long long pack2(float lo, float hi) {
    unsigned long long r;
    asm("mov.b64 %0, {%1, %2};" : "=l"(r)
        : "r"(__float_as_uint(lo)), "r"(__float_as_uint(hi)));
    return r;
}
__device__ __forceinline__ void unpack2(unsigned long long v, float& lo, float& hi) {
    unsigned int a, b;
    asm("mov.b64 {%0, %1}, %2;" : "=r"(a), "=r"(b) : "l"(v));
    lo = __uint_as_float(a);
    hi = __uint_as_float(b);
}
__device__ __forceinline__ unsigned long long fma2(unsigned long long a,
                                                   unsigned long long b,
                                                   unsigned long long c) {
    unsigned long long d;
    asm("fma.rn.f32x2 %0, %1, %2, %3;" : "=l"(d) : "l"(a), "l"(b), "l"(c));
    return d;
}
__device__ __forceinline__ float tanh_fast(float x) {
    float y;
    asm("tanh.approx.f32 %0, %1;" : "=f"(y) : "f"(x));
    return y;
}

// ---------------------------------------------------------------------------
// Main fused kernel: scores[row] = sum_h tanh( (A @ Ws)[row,h] + Wresp[b,h] ) * w[h]
// A = spk_emb viewed as [131072, 512]. BM=128 rows/block, 4 col-chunks of 128,
// K-tiles of 16, double-buffered SMEM, 8x8 per-thread microtile with fma.f32x2.
// ---------------------------------------------------------------------------
__global__ __launch_bounds__(256, 2)
void score_kernel(const float* __restrict__ A,     // [131072,512]
                  const float* __restrict__ Ws,    // [512,512]
                  const float* __restrict__ Wresp, // [512,512]
                  const float* __restrict__ wvec,  // [512]
                  float* __restrict__ scores)      // [131072]
{
    __shared__ float As[2][16][128];   // transposed: As[k][row]
    __shared__ float Bs[2][16][128];   // Bs[k][col]
    __shared__ float s_score[128];

    const int tid = threadIdx.x;
    const int tx = tid & 15;           // col group
    const int ty = tid >> 4;           // row group
    const int row0 = blockIdx.x * 128;
    const int b = row0 >> 8;           // 256 rows per batch, BM=128 divides 256

    if (tid < 128) s_score[tid] = 0.0f;
    __syncthreads();

    // A-tile load mapping: 512 float4 slots; slot idx -> row=idx>>2, col4=idx&3
    const int ar0 = tid >> 2;              // rows 0..63
    const int ar1 = ar0 + 64;              // rows 64..127
    const int ac0 = (tid & 3) * 4;         // col within 16-wide k tile
    // B-tile: 512 float4 slots; idx -> krow=idx>>5, col4=idx&31
    const int bk0 = tid >> 5;              // k rows 0..7
    const int bk1 = bk0 + 8;               // k rows 8..15
    const int bc0 = (tid & 31) * 4;

    const float* Ab = A + (size_t)row0 * Hh;

    for (int cc = 0; cc < 4; cc++) {
        const int col0 = cc * 128;

        unsigned long long acc[8][4];
        #pragma unroll
        for (int i = 0; i < 8; i++)
            #pragma unroll
            for (int j = 0; j < 4; j++) acc[i][j] = 0ull;

        float4 ra0, ra1, rb0, rb1;

        // prologue: stage kt=0
        ra0 = *(const float4*)(Ab + (size_t)ar0 * Hh + ac0);
        ra1 = *(const float4*)(Ab + (size_t)ar1 * Hh + ac0);
        rb0 = *(const float4*)(Ws + (size_t)bk0 * Hh + col0 + bc0);
        rb1 = *(const float4*)(Ws + (size_t)bk1 * Hh + col0 + bc0);
        {
            As[0][ac0 + 0][ar0] = ra0.x; As[0][ac0 + 1][ar0] = ra0.y;
            As[0][ac0 + 2][ar0] = ra0.z; As[0][ac0 + 3][ar0] = ra0.w;
            As[0][ac0 + 0][ar1] = ra1.x; As[0][ac0 + 1][ar1] = ra1.y;
            As[0][ac0 + 2][ar1] = ra1.z; As[0][ac0 + 3][ar1] = ra1.w;
            *(float4*)&Bs[0][bk0][bc0] = rb0;
            *(float4*)&Bs[0][bk1][bc0] = rb1;
        }
        __syncthreads();

        #pragma unroll 1
        for (int kt = 0; kt < 32; kt++) {
            const int cur = kt & 1;
            if (kt < 31) {
                const int k0 = (kt + 1) * 16;
                ra0 = *(const float4*)(Ab + (size_t)ar0 * Hh + k0 + ac0);
                ra1 = *(const float4*)(Ab + (size_t)ar1 * Hh + k0 + ac0);
                rb0 = *(const float4*)(Ws + (size_t)(k0 + bk0) * Hh + col0 + bc0);
                rb1 = *(const float4*)(Ws + (size_t)(k0 + bk1) * Hh + col0 + bc0);
            }

            #pragma unroll
            for (int k = 0; k < 16; k++) {
                float4 af0 = *(const float4*)&As[cur][k][ty * 8];
                float4 af1 = *(const float4*)&As[cur][k][ty * 8 + 4];
                float4 bf0 = *(const float4*)&Bs[cur][k][tx * 8];
                float4 bf1 = *(const float4*)&Bs[cur][k][tx * 8 + 4];
                unsigned long long bb[4];
                bb[0] = pack2(bf0.x, bf0.y); bb[1] = pack2(bf0.z, bf0.w);
                bb[2] = pack2(bf1.x, bf1.y); bb[3] = pack2(bf1.z, bf1.w);
                float aa[8] = {af0.x, af0.y, af0.z, af0.w,
                               af1.x, af1.y, af1.z, af1.w};
                #pragma unroll
                for (int i = 0; i < 8; i++) {
                    unsigned long long ad = pack2(aa[i], aa[i]);
                    #pragma unroll
                    for (int j = 0; j < 4; j++)
                        acc[i][j] = fma2(ad, bb[j], acc[i][j]);
                }
            }

            if (kt < 31) {
                const int nxt = (kt + 1) & 1;
                As[nxt][ac0 + 0][ar0] = ra0.x; As[nxt][ac0 + 1][ar0] = ra0.y;
                As[nxt][ac0 + 2][ar0] = ra0.z; As[nxt][ac0 + 3][ar0] = ra0.w;
                As[nxt][ac0 + 0][ar1] = ra1.x; As[nxt][ac0 + 1][ar1] = ra1.y;
                As[nxt][ac0 + 2][ar1] = ra1.z; As[nxt][ac0 + 3][ar1] = ra1.w;
                *(float4*)&Bs[nxt][bk0][bc0] = rb0;
                *(float4*)&Bs[nxt][bk1][bc0] = rb1;
            }
            __syncthreads();
        }

        // epilogue: tanh(c + Wresp) * w, reduce over this block's 8 cols
        float wr[8], wv[8];
        #pragma unroll
        for (int j = 0; j < 8; j++) {
            const int col = col0 + tx * 8 + j;
            wr[j] = Wresp[b * Hh + col];
            wv[j] = wvec[col];
        }
        #pragma unroll
        for (int i = 0; i < 8; i++) {
            float p = 0.0f;
            #pragma unroll
            for (int j2 = 0; j2 < 4; j2++) {
                float clo, chi;
                unpack2(acc[i][j2], clo, chi);
                p += tanh_fast(clo + wr[j2 * 2]) * wv[j2 * 2];
                p += tanh_fast(chi + wr[j2 * 2 + 1]) * wv[j2 * 2 + 1];
            }
            atomicAdd(&s_score[ty * 8 + i], p);
        }
        __syncthreads();
    }

    if (tid < 128) scores[(size_t)row0 + tid] = s_score[tid];
}

// ---------------------------------------------------------------------------
// Per-batch softmax (with mask scaling) + resp_s = alpha . spk_emb
// ---------------------------------------------------------------------------
__global__ __launch_bounds__(256)
void softmax_weight_kernel(const float* __restrict__ scores,
                           const float* __restrict__ mask,
                           const float* __restrict__ emb,
                           float* __restrict__ alpha_out,
                           float* __restrict__ resps)
{
    const int b = blockIdx.x;
    const int tid = threadIdx.x;   // 256 threads, one per n
    __shared__ float sa[256];
    __shared__ float red[256];

    const float t = scores[b * Nn + tid] * mask[b * Nn + tid];

    red[tid] = t; __syncthreads();
    #pragma unroll
    for (int s = 128; s > 0; s >>= 1) {
        if (tid < s) red[tid] = fmaxf(red[tid], red[tid + s]);
        __syncthreads();
    }
    const float m = red[0];
    __syncthreads();

    const float e = __expf(t - m);
    red[tid] = e; __syncthreads();
    #pragma unroll
    for (int s = 128; s > 0; s >>= 1) {
        if (tid < s) red[tid] += red[tid + s];
        __syncthreads();
    }
    const float a = e / red[0];

    alpha_out[b * Nn + tid] = a;
    sa[tid] = a;
    __syncthreads();

    const float* eb = emb + (size_t)b * Nn * Hh;
    float acc0 = 0.0f, acc1 = 0.0f;
    const int h = tid;
    #pragma unroll 4
    for (int n = 0; n < Nn; n++) {
        const float al = sa[n];
        const float* p = eb + (size_t)n * Hh;
        acc0 = fmaf(al, p[h], acc0);
        acc1 = fmaf(al, p[h + 256], acc1);
    }
    resps[b * Hh + h] = acc0;
    resps[b * Hh + h + 256] = acc1;
}

// ---------------------------------------------------------------------------
// Small 512x512x512 GEMM: out = act(A @ op(B) [+ Cadd])
//   TRANSB: op(B)=B^T (B stored [out,in]);  DOADD: += Cadd;  DOTANH: tanh
// ---------------------------------------------------------------------------
template <bool TRANSB, bool DOADD, bool DOTANH>
__global__ __launch_bounds__(1024)
void gemm512_kernel(const float* __restrict__ A,
                    const float* __restrict__ B,
                    const float* __restrict__ Cadd,
                    float* __restrict__ out)
{
    __shared__ float As[32][33];
    __shared__ float Bs[32][33];
    const int tx = threadIdx.x, ty = threadIdx.y;
    const int col0 = blockIdx.x * 32, row0 = blockIdx.y * 32;
    float acc = 0.0f;

    for (int kt = 0; kt < 16; kt++) {
        const int k0 = kt * 32;
        As[ty][tx] = A[(row0 + ty) * Hh + k0 + tx];
        if (TRANSB)
            Bs[ty][tx] = B[(col0 + ty) * Hh + k0 + tx];   // Bs[c][k]
        else
            Bs[ty][tx] = B[(k0 + ty) * Hh + col0 + tx];   // Bs[k][c]
        __syncthreads();
        #pragma unroll
        for (int k = 0; k < 32; k++)
            acc = fmaf(As[ty][k], TRANSB ? Bs[tx][k] : Bs[k][tx], acc);
        __syncthreads();
    }

    const int idx = (row0 + ty) * Hh + col0 + tx;
    float v = acc;
    if (DOADD) v += Cadd[idx];
    if (DOTANH) v = tanhf(v);
    out[idx] = v;
}

// ---------------------------------------------------------------------------
extern "C" void kernel_launch(void* const* d_in, const int* in_sizes, int n_in,
                              void* d_out, int out_size)
{
    const float* spk  = (const float*)d_in[0];  // [512,256,512]
    const float* mask = (const float*)d_in[1];  // [512,256]
    const float* tr   = (const float*)d_in[2];  // [512,512]
    const float* Ws   = (const float*)d_in[3];  // [512,512]
    const float* Wr   = (const float*)d_in[4];  // [512,512]
    const float* w    = (const float*)d_in[5];  // [512,1]
    const float* Wp   = (const float*)d_in[6];  // [512,512]
    const float* Wx   = (const float*)d_in[7];  // [512,512]

    float* out = (float*)d_out;
    float* resp_out  = out;                 // [512*512]
    float* alpha_out = out + Bsz * Hh;      // [512*256]

    float *pWresp, *prx, *pscores, *presps;
    cudaGetSymbolAddress((void**)&pWresp, g_Wresp);
    cudaGetSymbolAddress((void**)&prx, g_rx);
    cudaGetSymbolAddress((void**)&pscores, g_scores);
    cudaGetSymbolAddress((void**)&presps, g_resps);

    dim3 gb(16, 16), tb(32, 32);

    // W_resp = true_resp @ W_r
    gemm512_kernel<false, false, false><<<gb, tb>>>(tr, Wr, nullptr, pWresp);
    // rx = true_resp @ Wx^T
    gemm512_kernel<true, false, false><<<gb, tb>>>(tr, Wx, nullptr, prx);
    // fused big GEMM + tanh + dot(w)
    score_kernel<<<1024, 256>>>(spk, Ws, pWresp, w, pscores);
    // softmax + weighted sum
    softmax_weight_kernel<<<Bsz, 256>>>(pscores, mask, spk, alpha_out, presps);
    // out = tanh(resps @ Wp^T + rx)
    gemm512_kernel<true, true, true><<<gb, tb>>>(presps, Wp, prx, resp_out);
}

// round 4
// speedup vs baseline: 1.3509x; 1.3509x over previous
#include <cuda_runtime.h>
#include <cuda_bf16.h>
#include <cstdint>

// ---------------------------------------------------------------------------
// Spk_Attention: B=512, N=256, H=512.  Plain sm_103 target (no tcgen05) ->
// sm_80 mma.sync tf32 path with 3xTF32 error compensation (fp32-accurate).
// ---------------------------------------------------------------------------

#define Bsz 512
#define Nn  256
#define Hh  512
#define PAD 36          // k-tile row pad (floats): frag LDS conflict-free

__device__ float g_Wresp[Bsz * Hh];
__device__ float g_rx[Bsz * Hh];
__device__ float g_scores_part[4 * Bsz * Nn];   // per col-chunk partials
__device__ float g_resps[Bsz * Hh];
__device__ float g_WsT[Hh * Hh];

// ---------------- helpers --------------------------------------------------
__device__ __forceinline__ float tanh_fast(float x) {
    float y;
    asm("tanh.approx.f32 %0, %1;" : "=f"(y) : "f"(x));
    return y;
}
__device__ __forceinline__ uint32_t smem_u32(const void* p) {
    uint32_t a;
    asm("{ .reg .u64 t; cvta.to.shared.u64 t, %1; cvt.u32.u64 %0, t; }"
        : "=r"(a) : "l"(p));
    return a;
}
__device__ __forceinline__ void cp16(uint32_t dst, const void* src) {
    asm volatile("cp.async.cg.shared.global [%0], [%1], 16;"
                 :: "r"(dst), "l"(src) : "memory");
}
__device__ __forceinline__ void mma_tf32(float* d, const uint32_t* a,
                                         const uint32_t* b) {
    asm volatile(
        "mma.sync.aligned.m16n8k8.row.col.f32.tf32.tf32.f32 "
        "{%0,%1,%2,%3}, {%4,%5,%6,%7}, {%8,%9}, {%0,%1,%2,%3};"
        : "+f"(d[0]), "+f"(d[1]), "+f"(d[2]), "+f"(d[3])
        : "r"(a[0]), "r"(a[1]), "r"(a[2]), "r"(a[3]),
          "r"(b[0]), "r"(b[1]));
}
// 3xTF32 split: v = hi + lo (each tf32-representable)
__device__ __forceinline__ void split_tf32(float v, uint32_t& hi, uint32_t& lo) {
    asm("cvt.rna.tf32.f32 %0, %1;" : "=r"(hi) : "f"(v));
    float r = v - __uint_as_float(hi);
    asm("cvt.rna.tf32.f32 %0, %1;" : "=r"(lo) : "f"(r));
}

// ---------------------------------------------------------------------------
// score partial kernel: CTA = 128 rows x 128 cols, K = 512.
// grid = (1024 row-blocks, 4 col-chunks). 3xTF32 mma.sync.
// Epilogue: tanh(v + Wresp[b,col]) * w[col], reduce over 128 cols,
// deterministic partial -> g_scores_part[chunk][row].
// ---------------------------------------------------------------------------
#define SM_FLOATS (4 * 128 * PAD + 2 * 128 + 256)

__global__ __launch_bounds__(256, 2)
void score_mma(const float* __restrict__ A,      // spk_emb [131072,512]
               const float* __restrict__ BT,     // WsT [n][k]
               const float* __restrict__ Wresp,  // [512,512]
               const float* __restrict__ wvec,   // [512]
               float* __restrict__ scores_part)  // [4][131072]
{
    extern __shared__ float sm[];
    float* sA[2] = { sm,               sm + 128 * PAD };
    float* sB[2] = { sm + 2*128*PAD,   sm + 3*128*PAD };
    float* WRs = sm + 4 * 128 * PAD;
    float* WVs = WRs + 128;
    float* sp2 = WVs + 128;            // [2][128] per-wn partials

    const int tid  = threadIdx.x;
    const int lane = tid & 31, wid = tid >> 5;
    const int wm = wid & 3, wn = wid >> 2;         // 4 x 2 warp grid
    const int g  = lane >> 2, tg = lane & 3;
    const int row0 = blockIdx.x * 128;
    const int col0 = blockIdx.y * 128;
    const int b    = row0 >> 8;

    if (tid < 128) {
        WRs[tid] = Wresp[b * Hh + col0 + tid];
        WVs[tid] = wvec[col0 + tid];
    }

    const uint32_t sbase = smem_u32(sm);
    const uint32_t aoff[2] = { 0u, (uint32_t)(128 * PAD * 4) };
    const uint32_t boff[2] = { (uint32_t)(2*128*PAD*4), (uint32_t)(3*128*PAD*4) };

    auto load_stage = [&](int kk, int buf) {
        const float* Ag = A  + (size_t)row0 * Hh + kk * 32;
        const float* Bg = BT + (size_t)col0 * Hh + kk * 32;
        #pragma unroll
        for (int i = 0; i < 4; i++) {
            int idx = tid + 256 * i;
            int r = idx >> 3, c = idx & 7;
            uint32_t d = (uint32_t)(r * (PAD * 4) + c * 16);
            cp16(sbase + aoff[buf] + d, Ag + (size_t)r * Hh + c * 4);
            cp16(sbase + boff[buf] + d, Bg + (size_t)r * Hh + c * 4);
        }
        asm volatile("cp.async.commit_group;" ::: "memory");
    };

    load_stage(0, 0);
    load_stage(1, 1);

    float acc[2][8][4];
    #pragma unroll
    for (int mt = 0; mt < 2; mt++)
        #pragma unroll
        for (int nt = 0; nt < 8; nt++)
            #pragma unroll
            for (int c = 0; c < 4; c++) acc[mt][nt][c] = 0.0f;

    #pragma unroll 1
    for (int kk = 0; kk < 16; kk++) {
        if (kk < 15) asm volatile("cp.async.wait_group 1;" ::: "memory");
        else         asm volatile("cp.async.wait_group 0;" ::: "memory");
        __syncthreads();

        const float* As = sA[kk & 1];
        const float* Bs = sB[kk & 1];

        #pragma unroll
        for (int ks = 0; ks < 4; ks++) {
            const int k0 = ks * 8;
            uint32_t ah[2][4], al[2][4];
            #pragma unroll
            for (int mt = 0; mt < 2; mt++) {
                const int rb = wm * 32 + mt * 16;
                split_tf32(As[(rb + g    ) * PAD + k0 + tg    ], ah[mt][0], al[mt][0]);
                split_tf32(As[(rb + 8 + g) * PAD + k0 + tg    ], ah[mt][1], al[mt][1]);
                split_tf32(As[(rb + g    ) * PAD + k0 + tg + 4], ah[mt][2], al[mt][2]);
                split_tf32(As[(rb + 8 + g) * PAD + k0 + tg + 4], ah[mt][3], al[mt][3]);
            }
            #pragma unroll
            for (int nt = 0; nt < 8; nt++) {
                const int cb = wn * 64 + nt * 8;
                uint32_t bh[2], bl[2];
                split_tf32(Bs[(cb + g) * PAD + k0 + tg    ], bh[0], bl[0]);
                split_tf32(Bs[(cb + g) * PAD + k0 + tg + 4], bh[1], bl[1]);
                #pragma unroll
                for (int mt = 0; mt < 2; mt++) {
                    mma_tf32(acc[mt][nt], al[mt], bh);   // lo*hi
                    mma_tf32(acc[mt][nt], ah[mt], bl);   // hi*lo
                    mma_tf32(acc[mt][nt], ah[mt], bh);   // hi*hi
                }
            }
        }
        __syncthreads();
        if (kk + 2 < 16) load_stage(kk + 2, kk & 1);
    }

    // epilogue: tanh + dot(w), reduce over this CTA's 128 cols (deterministic)
    #pragma unroll
    for (int mt = 0; mt < 2; mt++) {
        float plo = 0.0f, phi = 0.0f;
        #pragma unroll
        for (int nt = 0; nt < 8; nt++) {
            const int c0 = wn * 64 + nt * 8 + 2 * tg;
            const int c1 = c0 + 1;
            plo += tanh_fast(acc[mt][nt][0] + WRs[c0]) * WVs[c0]
                 + tanh_fast(acc[mt][nt][1] + WRs[c1]) * WVs[c1];
            phi += tanh_fast(acc[mt][nt][2] + WRs[c0]) * WVs[c0]
                 + tanh_fast(acc[mt][nt][3] + WRs[c1]) * WVs[c1];
        }
        plo += __shfl_xor_sync(0xFFFFFFFFu, plo, 1);
        plo += __shfl_xor_sync(0xFFFFFFFFu, plo, 2);
        phi += __shfl_xor_sync(0xFFFFFFFFu, phi, 1);
        phi += __shfl_xor_sync(0xFFFFFFFFu, phi, 2);
        if (tg == 0) {
            sp2[wn * 128 + wm * 32 + mt * 16 + g]     = plo;
            sp2[wn * 128 + wm * 32 + mt * 16 + 8 + g] = phi;
        }
    }
    __syncthreads();
    if (tid < 128)
        scores_part[(size_t)blockIdx.y * (Bsz * Nn) + row0 + tid] =
            sp2[tid] + sp2[128 + tid];
}

// ---------------------------------------------------------------------------
// 512x512 transpose
// ---------------------------------------------------------------------------
__global__ __launch_bounds__(1024)
void transpose512(const float* __restrict__ W, float* __restrict__ WT) {
    __shared__ float t[32][33];
    int x = blockIdx.x * 32 + threadIdx.x;
    int y = blockIdx.y * 32 + threadIdx.y;
    t[threadIdx.y][threadIdx.x] = W[y * Hh + x];
    __syncthreads();
    x = blockIdx.y * 32 + threadIdx.x;
    y = blockIdx.x * 32 + threadIdx.y;
    WT[y * Hh + x] = t[threadIdx.x][threadIdx.y];
}

// ---------------------------------------------------------------------------
// Per-batch softmax (sums 4 score partials in fixed order, applies mask)
// + resp_s = alpha . spk_emb   (512 threads, one h per thread)
// ---------------------------------------------------------------------------
__global__ __launch_bounds__(512)
void softmax_weight_kernel(const float* __restrict__ scores_part,
                           const float* __restrict__ mask,
                           const float* __restrict__ emb,
                           float* __restrict__ alpha_out,
                           float* __restrict__ resps)
{
    const int b = blockIdx.x;
    const int tid = threadIdx.x;
    __shared__ float sa[256];
    __shared__ float red[512];

    float t = -1e30f;
    if (tid < Nn) {
        const size_t i = (size_t)b * Nn + tid;
        float s = scores_part[i];
        s += scores_part[(size_t)(Bsz * Nn) + i];
        s += scores_part[(size_t)(2 * Bsz * Nn) + i];
        s += scores_part[(size_t)(3 * Bsz * Nn) + i];
        t = s * mask[i];
    }

    red[tid] = t; __syncthreads();
    #pragma unroll
    for (int s = 256; s > 0; s >>= 1) {
        if (tid < s) red[tid] = fmaxf(red[tid], red[tid + s]);
        __syncthreads();
    }
    const float m = red[0];
    __syncthreads();

    const float e = (tid < Nn) ? __expf(t - m) : 0.0f;
    red[tid] = e; __syncthreads();
    #pragma unroll
    for (int s = 256; s > 0; s >>= 1) {
        if (tid < s) red[tid] += red[tid + s];
        __syncthreads();
    }
    const float a = e / red[0];

    if (tid < Nn) {
        alpha_out[(size_t)b * Nn + tid] = a;
        sa[tid] = a;
    }
    __syncthreads();

    const float* eb = emb + (size_t)b * Nn * Hh;
    float acc = 0.0f;
    #pragma unroll 8
    for (int n = 0; n < Nn; n++)
        acc = fmaf(sa[n], eb[(size_t)n * Hh + tid], acc);
    resps[b * Hh + tid] = acc;
}

// ---------------------------------------------------------------------------
// Small 512x512x512 GEMM: out = act(A @ op(B) [+ Cadd])
// ---------------------------------------------------------------------------
template <bool TRANSB, bool DOADD, bool DOTANH>
__global__ __launch_bounds__(1024)
void gemm512_kernel(const float* __restrict__ A,
                    const float* __restrict__ B,
                    const float* __restrict__ Cadd,
                    float* __restrict__ out)
{
    __shared__ float As[32][33];
    __shared__ float Bs[32][33];
    const int tx = threadIdx.x, ty = threadIdx.y;
    const int col0 = blockIdx.x * 32, row0 = blockIdx.y * 32;
    float acc = 0.0f;

    for (int kt = 0; kt < 16; kt++) {
        const int k0 = kt * 32;
        As[ty][tx] = A[(row0 + ty) * Hh + k0 + tx];
        if (TRANSB)
            Bs[ty][tx] = B[(col0 + ty) * Hh + k0 + tx];
        else
            Bs[ty][tx] = B[(k0 + ty) * Hh + col0 + tx];
        __syncthreads();
        #pragma unroll
        for (int k = 0; k < 32; k++)
            acc = fmaf(As[ty][k], TRANSB ? Bs[tx][k] : Bs[k][tx], acc);
        __syncthreads();
    }

    const int idx = (row0 + ty) * Hh + col0 + tx;
    float v = acc;
    if (DOADD) v += Cadd[idx];
    if (DOTANH) v = tanhf(v);
    out[idx] = v;
}

// ---------------------------------------------------------------------------
extern "C" void kernel_launch(void* const* d_in, const int* in_sizes, int n_in,
                              void* d_out, int out_size)
{
    const float* spk  = (const float*)d_in[0];  // [512,256,512]
    const float* mask = (const float*)d_in[1];  // [512,256]
    const float* tr   = (const float*)d_in[2];  // [512,512]
    const float* Ws   = (const float*)d_in[3];  // [512,512]
    const float* Wr   = (const float*)d_in[4];  // [512,512]
    const float* w    = (const float*)d_in[5];  // [512,1]
    const float* Wp   = (const float*)d_in[6];  // [512,512]
    const float* Wx   = (const float*)d_in[7];  // [512,512]

    float* out = (float*)d_out;
    float* resp_out  = out;
    float* alpha_out = out + Bsz * Hh;

    float *pWresp, *prx, *pspart, *presps, *pWsT;
    cudaGetSymbolAddress((void**)&pWresp, g_Wresp);
    cudaGetSymbolAddress((void**)&prx, g_rx);
    cudaGetSymbolAddress((void**)&pspart, g_scores_part);
    cudaGetSymbolAddress((void**)&presps, g_resps);
    cudaGetSymbolAddress((void**)&pWsT, g_WsT);

    static bool attr_set = false;
    if (!attr_set) {
        cudaFuncSetAttribute(score_mma,
                             cudaFuncAttributeMaxDynamicSharedMemorySize,
                             SM_FLOATS * 4);
        attr_set = true;
    }

    dim3 gb(16, 16), tb(32, 32);

    // WsT = Ws^T (K-major B operand)
    transpose512<<<dim3(16, 16), dim3(32, 32)>>>(Ws, pWsT);
    // W_resp = true_resp @ W_r
    gemm512_kernel<false, false, false><<<gb, tb>>>(tr, Wr, nullptr, pWresp);
    // rx = true_resp @ Wx^T
    gemm512_kernel<true, false, false><<<gb, tb>>>(tr, Wx, nullptr, prx);
    // score partials (3xTF32 tensor cores)
    score_mma<<<dim3(1024, 4), 256, SM_FLOATS * 4>>>(spk, pWsT, pWresp, w, pspart);
    // softmax + weighted sum
    softmax_weight_kernel<<<Bsz, 512>>>(pspart, mask, spk, alpha_out, presps);
    // out = tanh(resps @ Wp^T + rx)
    gemm512_kernel<true, true, true><<<gb, tb>>>(presps, Wp, prx, resp_out);
}

// round 5
// speedup vs baseline: 1.8042x; 1.3355x over previous
#include <cuda_runtime.h>
#include <cuda_bf16.h>
#include <cstdint>

// ---------------------------------------------------------------------------
// Spk_Attention: B=512, N=256, H=512.  Plain sm_103 target (no tcgen05) ->
// sm_80 mma.sync bf16 m16n8k16 with 3xBF16 error compensation.
// Operands pre-split in GMEM as interleaved words: [hi bf16x2 | lo bf16x2].
// ---------------------------------------------------------------------------

#define Bsz 512
#define Nn  256
#define Hh  512

__device__ float    g_Wresp[Bsz * Hh];
__device__ float    g_rx[Bsz * Hh];
__device__ float    g_scores_part[4 * Bsz * Nn];
__device__ float    g_resps[Bsz * Hh];
__device__ uint32_t g_Asp[(size_t)Bsz * Nn * Hh];   // spk split: [131072][512] words
__device__ uint32_t g_Bsp[Hh * Hh];                 // WsT split: [512 n][512] words

// ---------------- helpers --------------------------------------------------
__device__ __forceinline__ float tanh_fast(float x) {
    float y;
    asm("tanh.approx.f32 %0, %1;" : "=f"(y) : "f"(x));
    return y;
}
__device__ __forceinline__ uint32_t smem_u32(const void* p) {
    uint32_t a;
    asm("{ .reg .u64 t; cvta.to.shared.u64 t, %1; cvt.u32.u64 %0, t; }"
        : "=r"(a) : "l"(p));
    return a;
}
__device__ __forceinline__ void cp16(uint32_t dst, const void* src) {
    asm volatile("cp.async.cg.shared.global [%0], [%1], 16;"
                 :: "r"(dst), "l"(src) : "memory");
}
__device__ __forceinline__ void mma_bf16(float* d, uint32_t a0, uint32_t a1,
                                         uint32_t a2, uint32_t a3,
                                         uint32_t b0, uint32_t b1) {
    asm volatile(
        "mma.sync.aligned.m16n8k16.row.col.f32.bf16.bf16.f32 "
        "{%0,%1,%2,%3}, {%4,%5,%6,%7}, {%8,%9}, {%0,%1,%2,%3};"
        : "+f"(d[0]), "+f"(d[1]), "+f"(d[2]), "+f"(d[3])
        : "r"(a0), "r"(a1), "r"(a2), "r"(a3), "r"(b0), "r"(b1));
}
// split two fp32 into (hi bf16x2 word, lo bf16x2 word)
__device__ __forceinline__ void split_pair(float x, float y,
                                           uint32_t& hi, uint32_t& lo) {
    __nv_bfloat16 hx = __float2bfloat16(x);
    __nv_bfloat16 hy = __float2bfloat16(y);
    float lxf = x - __bfloat162float(hx);
    float lyf = y - __bfloat162float(hy);
    __nv_bfloat162 h2, l2;
    h2.x = hx; h2.y = hy;
    l2.x = __float2bfloat16(lxf); l2.y = __float2bfloat16(lyf);
    hi = *(uint32_t*)&h2;
    lo = *(uint32_t*)&l2;
}

// ---------------------------------------------------------------------------
// pre-split kernels
// ---------------------------------------------------------------------------
__global__ __launch_bounds__(256)
void split_spk(const float* __restrict__ A, uint32_t* __restrict__ out) {
    const size_t j = (size_t)blockIdx.x * 256 + threadIdx.x;  // pair index
    const float2 v = ((const float2*)A)[j];
    uint2 w;
    split_pair(v.x, v.y, w.x, w.y);
    ((uint2*)out)[j] = w;   // words 2j (hi), 2j+1 (lo)
}

// WsT split: out[n][2p]=hi(Ws[2p][n],Ws[2p+1][n]), out[n][2p+1]=lo
__global__ __launch_bounds__(512)
void split_ws(const float* __restrict__ Ws, uint32_t* __restrict__ out) {
    const int p = blockIdx.x;        // 0..255
    const int n = threadIdx.x;       // 0..511
    const float x = Ws[(2 * p) * Hh + n];
    const float y = Ws[(2 * p + 1) * Hh + n];
    uint32_t hi, lo;
    split_pair(x, y, hi, lo);
    out[(size_t)n * Hh + 2 * p]     = hi;
    out[(size_t)n * Hh + 2 * p + 1] = lo;
}

// ---------------------------------------------------------------------------
// score partial kernel: CTA = 128 rows x 128 cols, K = 512.
// grid = (1024 row-blocks, 4 col-chunks). 3xBF16 mma.sync m16n8k16.
// SMEM word rows: 32 data words (16 hi|lo pairs = k-tile of 32) + 8 pad.
// ---------------------------------------------------------------------------
#define W40 40
#define TILE_WORDS (128 * W40)                         // 5120
#define SM_WORDS   (4 * TILE_WORDS + 512)              // A0 A1 B0 B1 + WR/WV/sp2
#define SM_BYTES   (SM_WORDS * 4)

__global__ __launch_bounds__(256, 2)
void score_mma(const uint32_t* __restrict__ Asp,   // [131072][512] words
               const uint32_t* __restrict__ Bsp,   // [512][512] words
               const float* __restrict__ Wresp,    // [512,512]
               const float* __restrict__ wvec,     // [512]
               float* __restrict__ scores_part)    // [4][131072]
{
    extern __shared__ uint32_t smw[];
    uint32_t* sA[2] = { smw,                  smw + TILE_WORDS };
    uint32_t* sB[2] = { smw + 2 * TILE_WORDS, smw + 3 * TILE_WORDS };
    float* WRs = (float*)(smw + 4 * TILE_WORDS);
    float* WVs = WRs + 128;
    float* sp2 = WVs + 128;   // [2][128]

    const int tid  = threadIdx.x;
    const int lane = tid & 31, wid = tid >> 5;
    const int wm = wid & 3, wn = wid >> 2;     // 4 x 2 warp grid
    const int g  = lane >> 2, tg = lane & 3;
    const int row0 = blockIdx.x * 128;
    const int col0 = blockIdx.y * 128;
    const int b    = row0 >> 8;

    if (tid < 128) {
        WRs[tid] = Wresp[b * Hh + col0 + tid];
        WVs[tid] = wvec[col0 + tid];
    }

    const uint32_t sbase = smem_u32(smw);
    const uint32_t aoff[2] = { 0u, (uint32_t)(TILE_WORDS * 4) };
    const uint32_t boff[2] = { (uint32_t)(2 * TILE_WORDS * 4),
                               (uint32_t)(3 * TILE_WORDS * 4) };

    // stage: 128 rows x 32 words (128B) per matrix; 8 chunks of 16B per row
    auto load_stage = [&](int kk, int buf) {
        const char* Ag = (const char*)(Asp + (size_t)row0 * 512 + kk * 32);
        const char* Bg = (const char*)(Bsp + (size_t)col0 * 512 + kk * 32);
        #pragma unroll
        for (int i = 0; i < 4; i++) {
            int idx = tid + 256 * i;
            int r = idx >> 3, c = idx & 7;
            uint32_t d = (uint32_t)(r * (W40 * 4) + c * 16);
            cp16(sbase + aoff[buf] + d, Ag + (size_t)r * 2048 + c * 16);
            cp16(sbase + boff[buf] + d, Bg + (size_t)r * 2048 + c * 16);
        }
        asm volatile("cp.async.commit_group;" ::: "memory");
    };

    load_stage(0, 0);
    load_stage(1, 1);

    float acc[2][8][4];
    #pragma unroll
    for (int mt = 0; mt < 2; mt++)
        #pragma unroll
        for (int nt = 0; nt < 8; nt++)
            #pragma unroll
            for (int c = 0; c < 4; c++) acc[mt][nt][c] = 0.0f;

    #pragma unroll 1
    for (int kk = 0; kk < 16; kk++) {
        if (kk < 15) asm volatile("cp.async.wait_group 1;" ::: "memory");
        else         asm volatile("cp.async.wait_group 0;" ::: "memory");
        __syncthreads();

        const uint32_t* As = sA[kk & 1];
        const uint32_t* Bs = sB[kk & 1];

        #pragma unroll
        for (int ks = 0; ks < 2; ks++) {
            const int w0 = ks * 16 + 2 * tg;   // word offset of pair tg in k16 window
            // A fragments: uint2 = {hi word, lo word}
            uint2 vA[2][4];
            #pragma unroll
            for (int mt = 0; mt < 2; mt++) {
                const int rb = wm * 32 + mt * 16;
                vA[mt][0] = *(const uint2*)&As[(rb + g    ) * W40 + w0    ];
                vA[mt][1] = *(const uint2*)&As[(rb + 8 + g) * W40 + w0    ];
                vA[mt][2] = *(const uint2*)&As[(rb + g    ) * W40 + w0 + 8];
                vA[mt][3] = *(const uint2*)&As[(rb + 8 + g) * W40 + w0 + 8];
            }
            #pragma unroll
            for (int nt = 0; nt < 8; nt++) {
                const int cb = wn * 64 + nt * 8;
                const uint2 vB0 = *(const uint2*)&Bs[(cb + g) * W40 + w0    ];
                const uint2 vB1 = *(const uint2*)&Bs[(cb + g) * W40 + w0 + 8];
                #pragma unroll
                for (int mt = 0; mt < 2; mt++) {
                    // lo*hi + hi*lo + hi*hi
                    mma_bf16(acc[mt][nt], vA[mt][0].y, vA[mt][1].y,
                             vA[mt][2].y, vA[mt][3].y, vB0.x, vB1.x);
                    mma_bf16(acc[mt][nt], vA[mt][0].x, vA[mt][1].x,
                             vA[mt][2].x, vA[mt][3].x, vB0.y, vB1.y);
                    mma_bf16(acc[mt][nt], vA[mt][0].x, vA[mt][1].x,
                             vA[mt][2].x, vA[mt][3].x, vB0.x, vB1.x);
                }
            }
        }
        __syncthreads();
        if (kk + 2 < 16) load_stage(kk + 2, kk & 1);
    }

    // epilogue: tanh + dot(w), reduce over 128 cols (deterministic)
    #pragma unroll
    for (int mt = 0; mt < 2; mt++) {
        float plo = 0.0f, phi = 0.0f;
        #pragma unroll
        for (int nt = 0; nt < 8; nt++) {
            const int c0 = wn * 64 + nt * 8 + 2 * tg;
            const int c1 = c0 + 1;
            plo += tanh_fast(acc[mt][nt][0] + WRs[c0]) * WVs[c0]
                 + tanh_fast(acc[mt][nt][1] + WRs[c1]) * WVs[c1];
            phi += tanh_fast(acc[mt][nt][2] + WRs[c0]) * WVs[c0]
                 + tanh_fast(acc[mt][nt][3] + WRs[c1]) * WVs[c1];
        }
        plo += __shfl_xor_sync(0xFFFFFFFFu, plo, 1);
        plo += __shfl_xor_sync(0xFFFFFFFFu, plo, 2);
        phi += __shfl_xor_sync(0xFFFFFFFFu, phi, 1);
        phi += __shfl_xor_sync(0xFFFFFFFFu, phi, 2);
        if (tg == 0) {
            sp2[wn * 128 + wm * 32 + mt * 16 + g]     = plo;
            sp2[wn * 128 + wm * 32 + mt * 16 + 8 + g] = phi;
        }
    }
    __syncthreads();
    if (tid < 128)
        scores_part[(size_t)blockIdx.y * (Bsz * Nn) + row0 + tid] =
            sp2[tid] + sp2[128 + tid];
}

// ---------------------------------------------------------------------------
// Per-batch softmax (sums 4 partials in fixed order, applies mask)
// + resp_s = alpha . spk_emb
// ---------------------------------------------------------------------------
__global__ __launch_bounds__(512)
void softmax_weight_kernel(const float* __restrict__ scores_part,
                           const float* __restrict__ mask,
                           const float* __restrict__ emb,
                           float* __restrict__ alpha_out,
                           float* __restrict__ resps)
{
    const int b = blockIdx.x;
    const int tid = threadIdx.x;
    __shared__ float sa[256];
    __shared__ float red[512];

    float t = -1e30f;
    if (tid < Nn) {
        const size_t i = (size_t)b * Nn + tid;
        float s = scores_part[i];
        s += scores_part[(size_t)(Bsz * Nn) + i];
        s += scores_part[(size_t)(2 * Bsz * Nn) + i];
        s += scores_part[(size_t)(3 * Bsz * Nn) + i];
        t = s * mask[i];
    }

    red[tid] = t; __syncthreads();
    #pragma unroll
    for (int s = 256; s > 0; s >>= 1) {
        if (tid < s) red[tid] = fmaxf(red[tid], red[tid + s]);
        __syncthreads();
    }
    const float m = red[0];
    __syncthreads();

    const float e = (tid < Nn) ? __expf(t - m) : 0.0f;
    red[tid] = e; __syncthreads();
    #pragma unroll
    for (int s = 256; s > 0; s >>= 1) {
        if (tid < s) red[tid] += red[tid + s];
        __syncthreads();
    }
    const float a = e / red[0];

    if (tid < Nn) {
        alpha_out[(size_t)b * Nn + tid] = a;
        sa[tid] = a;
    }
    __syncthreads();

    const float* eb = emb + (size_t)b * Nn * Hh;
    float acc = 0.0f;
    #pragma unroll 8
    for (int n = 0; n < Nn; n++)
        acc = fmaf(sa[n], eb[(size_t)n * Hh + tid], acc);
    resps[b * Hh + tid] = acc;
}

// ---------------------------------------------------------------------------
// Small 512x512x512 GEMM: out = act(A @ op(B) [+ Cadd])
// ---------------------------------------------------------------------------
template <bool TRANSB, bool DOADD, bool DOTANH>
__global__ __launch_bounds__(1024)
void gemm512_kernel(const float* __restrict__ A,
                    const float* __restrict__ B,
                    const float* __restrict__ Cadd,
                    float* __restrict__ out)
{
    __shared__ float As[32][33];
    __shared__ float Bs[32][33];
    const int tx = threadIdx.x, ty = threadIdx.y;
    const int col0 = blockIdx.x * 32, row0 = blockIdx.y * 32;
    float acc = 0.0f;

    for (int kt = 0; kt < 16; kt++) {
        const int k0 = kt * 32;
        As[ty][tx] = A[(row0 + ty) * Hh + k0 + tx];
        if (TRANSB)
            Bs[ty][tx] = B[(col0 + ty) * Hh + k0 + tx];
        else
            Bs[ty][tx] = B[(k0 + ty) * Hh + col0 + tx];
        __syncthreads();
        #pragma unroll
        for (int k = 0; k < 32; k++)
            acc = fmaf(As[ty][k], TRANSB ? Bs[tx][k] : Bs[k][tx], acc);
        __syncthreads();
    }

    const int idx = (row0 + ty) * Hh + col0 + tx;
    float v = acc;
    if (DOADD) v += Cadd[idx];
    if (DOTANH) v = tanhf(v);
    out[idx] = v;
}

// ---------------------------------------------------------------------------
extern "C" void kernel_launch(void* const* d_in, const int* in_sizes, int n_in,
                              void* d_out, int out_size)
{
    const float* spk  = (const float*)d_in[0];  // [512,256,512]
    const float* mask = (const float*)d_in[1];  // [512,256]
    const float* tr   = (const float*)d_in[2];  // [512,512]
    const float* Ws   = (const float*)d_in[3];  // [512,512]
    const float* Wr   = (const float*)d_in[4];  // [512,512]
    const float* w    = (const float*)d_in[5];  // [512,1]
    const float* Wp   = (const float*)d_in[6];  // [512,512]
    const float* Wx   = (const float*)d_in[7];  // [512,512]

    float* out = (float*)d_out;
    float* resp_out  = out;
    float* alpha_out = out + Bsz * Hh;

    float *pWresp, *prx, *pspart, *presps;
    uint32_t *pAsp, *pBsp;
    cudaGetSymbolAddress((void**)&pWresp, g_Wresp);
    cudaGetSymbolAddress((void**)&prx, g_rx);
    cudaGetSymbolAddress((void**)&pspart, g_scores_part);
    cudaGetSymbolAddress((void**)&presps, g_resps);
    cudaGetSymbolAddress((void**)&pAsp, g_Asp);
    cudaGetSymbolAddress((void**)&pBsp, g_Bsp);

    static bool attr_set = false;
    if (!attr_set) {
        cudaFuncSetAttribute(score_mma,
                             cudaFuncAttributeMaxDynamicSharedMemorySize,
                             SM_BYTES);
        attr_set = true;
    }

    dim3 gb(16, 16), tb(32, 32);

    // pre-split operands to bf16 hi|lo pairs
    split_spk<<<(Bsz * Nn * Hh / 2) / 256, 256>>>(spk, pAsp);
    split_ws<<<Hh / 2, Hh>>>(Ws, pBsp);
    // W_resp = true_resp @ W_r
    gemm512_kernel<false, false, false><<<gb, tb>>>(tr, Wr, nullptr, pWresp);
    // rx = true_resp @ Wx^T
    gemm512_kernel<true, false, false><<<gb, tb>>>(tr, Wx, nullptr, prx);
    // score partials (3xBF16 tensor cores)
    score_mma<<<dim3(1024, 4), 256, SM_BYTES>>>(pAsp, pBsp, pWresp, w, pspart);
    // softmax + weighted sum
    softmax_weight_kernel<<<Bsz, 512>>>(pspart, mask, spk, alpha_out, presps);
    // out = tanh(resps @ Wp^T + rx)
    gemm512_kernel<true, true, true><<<gb, tb>>>(presps, Wp, prx, resp_out);
}

// round 6
// speedup vs baseline: 2.1186x; 1.1742x over previous
#include <cuda_runtime.h>
#include <cuda_bf16.h>
#include <cstdint>

// ---------------------------------------------------------------------------
// Spk_Attention: B=512, N=256, H=512. sm_103 plain target -> mma.sync bf16
// m16n8k16 with 3xBF16 compensation. Operands pre-split into SEPARATE hi/lo
// bf16 planes; fragments loaded with ldmatrix.x4 (80B row stride,
// conflict-free).
// ---------------------------------------------------------------------------

#define Bsz 512
#define Nn  256
#define Hh  512

__device__ float g_Wresp[Bsz * Hh];
__device__ float g_rx[Bsz * Hh];
__device__ float g_scores_part[4 * Bsz * Nn];
__device__ float g_resps[Bsz * Hh];
__device__ __nv_bfloat16 g_Ahi[(size_t)Bsz * Nn * Hh];   // 128 MB
__device__ __nv_bfloat16 g_Alo[(size_t)Bsz * Nn * Hh];   // 128 MB
__device__ __nv_bfloat16 g_Bhi[Hh * Hh];                 // WsT hi plane [n][k]
__device__ __nv_bfloat16 g_Blo[Hh * Hh];

// ---------------- helpers --------------------------------------------------
__device__ __forceinline__ float tanh_fast(float x) {
    float y;
    asm("tanh.approx.f32 %0, %1;" : "=f"(y) : "f"(x));
    return y;
}
__device__ __forceinline__ uint32_t smem_u32(const void* p) {
    uint32_t a;
    asm("{ .reg .u64 t; cvta.to.shared.u64 t, %1; cvt.u32.u64 %0, t; }"
        : "=r"(a) : "l"(p));
    return a;
}
__device__ __forceinline__ void cp16(uint32_t dst, const void* src) {
    asm volatile("cp.async.cg.shared.global [%0], [%1], 16;"
                 :: "r"(dst), "l"(src) : "memory");
}
__device__ __forceinline__ void ldsm4(uint32_t* r, uint32_t addr) {
    asm volatile("ldmatrix.sync.aligned.m8n8.x4.shared.b16 {%0,%1,%2,%3}, [%4];"
                 : "=r"(r[0]), "=r"(r[1]), "=r"(r[2]), "=r"(r[3]) : "r"(addr));
}
__device__ __forceinline__ void mma_bf16(float* d, const uint32_t* a,
                                         uint32_t b0, uint32_t b1) {
    asm volatile(
        "mma.sync.aligned.m16n8k16.row.col.f32.bf16.bf16.f32 "
        "{%0,%1,%2,%3}, {%4,%5,%6,%7}, {%8,%9}, {%0,%1,%2,%3};"
        : "+f"(d[0]), "+f"(d[1]), "+f"(d[2]), "+f"(d[3])
        : "r"(a[0]), "r"(a[1]), "r"(a[2]), "r"(a[3]), "r"(b0), "r"(b1));
}
__device__ __forceinline__ void split1(float v, __nv_bfloat16& h,
                                       __nv_bfloat16& l) {
    h = __float2bfloat16(v);
    l = __float2bfloat16(v - __bfloat162float(h));
}

// ---------------------------------------------------------------------------
// pre-split kernels
// ---------------------------------------------------------------------------
__global__ __launch_bounds__(256)
void split_spk(const float* __restrict__ A,
               __nv_bfloat16* __restrict__ Ahi,
               __nv_bfloat16* __restrict__ Alo) {
    const size_t j = (size_t)blockIdx.x * 256 + threadIdx.x;   // pair idx
    const float2 v = ((const float2*)A)[j];
    __nv_bfloat162 h2, l2;
    split1(v.x, h2.x, l2.x);
    split1(v.y, h2.y, l2.y);
    ((__nv_bfloat162*)Ahi)[j] = h2;
    ((__nv_bfloat162*)Alo)[j] = l2;
}

// BT planes: Bhi[n][k] = bf16(Ws[k][n]) etc.
__global__ __launch_bounds__(512)
void split_ws(const float* __restrict__ Ws,
              __nv_bfloat16* __restrict__ Bhi,
              __nv_bfloat16* __restrict__ Blo) {
    const int p = blockIdx.x;        // k pair 0..255
    const int n = threadIdx.x;       // 0..511
    __nv_bfloat162 h2, l2;
    split1(Ws[(2 * p) * Hh + n],     h2.x, l2.x);
    split1(Ws[(2 * p + 1) * Hh + n], h2.y, l2.y);
    ((__nv_bfloat162*)Bhi)[(size_t)n * (Hh / 2) + p] = h2;
    ((__nv_bfloat162*)Blo)[(size_t)n * (Hh / 2) + p] = l2;
}

// ---------------------------------------------------------------------------
// score partial kernel: CTA = 128 rows x 128 cols, K = 512, 3xBF16 mma.sync,
// planes in SMEM with 80B row stride (32 bf16 data + 16B pad), ldmatrix.x4.
// ---------------------------------------------------------------------------
#define ROWB    80                      // bytes per 32-element bf16 row
#define PLANE_W (128 * 20)              // words per plane tile (20w = 80B)
#define STG_W   (4 * PLANE_W)           // Ahi Alo Bhi Blo
#define SM_W    (2 * STG_W + 512)
#define SM_BYTES (SM_W * 4)

__global__ __launch_bounds__(256, 2)
void score_mma(const __nv_bfloat16* __restrict__ Ahi,
               const __nv_bfloat16* __restrict__ Alo,
               const __nv_bfloat16* __restrict__ Bhi,
               const __nv_bfloat16* __restrict__ Blo,
               const float* __restrict__ Wresp,
               const float* __restrict__ wvec,
               float* __restrict__ scores_part)
{
    extern __shared__ uint32_t smw[];
    float* WRs = (float*)(smw + 2 * STG_W);
    float* WVs = WRs + 128;
    float* sp2 = WVs + 128;   // [2][128]

    const int tid  = threadIdx.x;
    const int lane = tid & 31, wid = tid >> 5;
    const int wm = wid & 3, wn = wid >> 2;     // 4 x 2 warp grid
    const int g  = lane >> 2, tg = lane & 3;
    const int row0 = blockIdx.x * 128;
    const int col0 = blockIdx.y * 128;
    const int b    = row0 >> 8;

    if (tid < 128) {
        WRs[tid] = Wresp[b * Hh + col0 + tid];
        WVs[tid] = wvec[col0 + tid];
    }

    const uint32_t sbase = smem_u32(smw);

    // ldmatrix per-lane address offsets (bytes) within a plane tile
    const uint32_t a_off = (((lane & 7) | (((lane >> 3) & 1) << 3)) * ROWB)
                           + ((lane >> 4) << 4);
    const uint32_t b_off = (((lane & 7) | (((lane >> 4) & 1) << 3)) * ROWB)
                           + (((lane >> 3) & 1) << 4);

    // stage loader: 4 planes x 128 rows x 64B = 2048 16B-chunks
    auto load_stage = [&](int kk, int buf) {
        const uint32_t db = sbase + (uint32_t)buf * (STG_W * 4);
        #pragma unroll
        for (int i = 0; i < 8; i++) {
            const int idx = tid + 256 * i;
            const int plane = idx >> 9;          // warp-uniform
            const int r = (idx >> 2) & 127;
            const int c = idx & 3;
            const __nv_bfloat16* src;
            if (plane == 0)
                src = Ahi + (size_t)(row0 + r) * Hh + kk * 32 + c * 8;
            else if (plane == 1)
                src = Alo + (size_t)(row0 + r) * Hh + kk * 32 + c * 8;
            else if (plane == 2)
                src = Bhi + (size_t)(col0 + r) * Hh + kk * 32 + c * 8;
            else
                src = Blo + (size_t)(col0 + r) * Hh + kk * 32 + c * 8;
            cp16(db + plane * (PLANE_W * 4) + r * ROWB + c * 16, src);
        }
        asm volatile("cp.async.commit_group;" ::: "memory");
    };

    load_stage(0, 0);
    load_stage(1, 1);

    float acc[2][8][4];
    #pragma unroll
    for (int mt = 0; mt < 2; mt++)
        #pragma unroll
        for (int nt = 0; nt < 8; nt++)
            #pragma unroll
            for (int c = 0; c < 4; c++) acc[mt][nt][c] = 0.0f;

    #pragma unroll 1
    for (int kk = 0; kk < 16; kk++) {
        if (kk < 15) asm volatile("cp.async.wait_group 1;" ::: "memory");
        else         asm volatile("cp.async.wait_group 0;" ::: "memory");
        __syncthreads();

        const uint32_t stg = sbase + (uint32_t)(kk & 1) * (STG_W * 4);
        const uint32_t pAhi = stg;
        const uint32_t pAlo = stg + PLANE_W * 4;
        const uint32_t pBhi = stg + 2 * PLANE_W * 4;
        const uint32_t pBlo = stg + 3 * PLANE_W * 4;

        #pragma unroll
        for (int ks = 0; ks < 2; ks++) {
            const uint32_t kso = ks * 32;
            uint32_t ahi[2][4], alo[2][4];
            #pragma unroll
            for (int mt = 0; mt < 2; mt++) {
                const uint32_t ro = (wm * 32 + mt * 16) * ROWB + kso;
                ldsm4(ahi[mt], pAhi + ro + a_off);
                ldsm4(alo[mt], pAlo + ro + a_off);
            }
            #pragma unroll
            for (int ntp = 0; ntp < 4; ntp++) {
                const uint32_t ro = (wn * 64 + ntp * 16) * ROWB + kso;
                uint32_t bh[4], bl[4];
                ldsm4(bh, pBhi + ro + b_off);
                ldsm4(bl, pBlo + ro + b_off);
                #pragma unroll
                for (int half = 0; half < 2; half++) {
                    const int nt = ntp * 2 + half;
                    const uint32_t b0h = bh[half * 2], b1h = bh[half * 2 + 1];
                    const uint32_t b0l = bl[half * 2], b1l = bl[half * 2 + 1];
                    #pragma unroll
                    for (int mt = 0; mt < 2; mt++) {
                        mma_bf16(acc[mt][nt], ahi[mt], b0l, b1l);  // hi*lo
                        mma_bf16(acc[mt][nt], alo[mt], b0h, b1h);  // lo*hi
                        mma_bf16(acc[mt][nt], ahi[mt], b0h, b1h);  // hi*hi
                    }
                }
            }
        }
        __syncthreads();
        if (kk + 2 < 16) load_stage(kk + 2, kk & 1);
    }

    // epilogue: tanh + dot(w), deterministic reduce over 128 cols
    #pragma unroll
    for (int mt = 0; mt < 2; mt++) {
        float plo = 0.0f, phi = 0.0f;
        #pragma unroll
        for (int nt = 0; nt < 8; nt++) {
            const int c0 = wn * 64 + nt * 8 + 2 * tg;
            const int c1 = c0 + 1;
            plo += tanh_fast(acc[mt][nt][0] + WRs[c0]) * WVs[c0]
                 + tanh_fast(acc[mt][nt][1] + WRs[c1]) * WVs[c1];
            phi += tanh_fast(acc[mt][nt][2] + WRs[c0]) * WVs[c0]
                 + tanh_fast(acc[mt][nt][3] + WRs[c1]) * WVs[c1];
        }
        plo += __shfl_xor_sync(0xFFFFFFFFu, plo, 1);
        plo += __shfl_xor_sync(0xFFFFFFFFu, plo, 2);
        phi += __shfl_xor_sync(0xFFFFFFFFu, phi, 1);
        phi += __shfl_xor_sync(0xFFFFFFFFu, phi, 2);
        if (tg == 0) {
            sp2[wn * 128 + wm * 32 + mt * 16 + g]     = plo;
            sp2[wn * 128 + wm * 32 + mt * 16 + 8 + g] = phi;
        }
    }
    __syncthreads();
    if (tid < 128)
        scores_part[(size_t)blockIdx.y * (Bsz * Nn) + row0 + tid] =
            sp2[tid] + sp2[128 + tid];
}

// ---------------------------------------------------------------------------
// Per-batch softmax + resp_s = alpha . spk_emb
// ---------------------------------------------------------------------------
__global__ __launch_bounds__(512)
void softmax_weight_kernel(const float* __restrict__ scores_part,
                           const float* __restrict__ mask,
                           const float* __restrict__ emb,
                           float* __restrict__ alpha_out,
                           float* __restrict__ resps)
{
    const int b = blockIdx.x;
    const int tid = threadIdx.x;
    __shared__ float sa[256];
    __shared__ float red[512];

    float t = -1e30f;
    if (tid < Nn) {
        const size_t i = (size_t)b * Nn + tid;
        float s = scores_part[i];
        s += scores_part[(size_t)(Bsz * Nn) + i];
        s += scores_part[(size_t)(2 * Bsz * Nn) + i];
        s += scores_part[(size_t)(3 * Bsz * Nn) + i];
        t = s * mask[i];
    }

    red[tid] = t; __syncthreads();
    #pragma unroll
    for (int s = 256; s > 0; s >>= 1) {
        if (tid < s) red[tid] = fmaxf(red[tid], red[tid + s]);
        __syncthreads();
    }
    const float m = red[0];
    __syncthreads();

    const float e = (tid < Nn) ? __expf(t - m) : 0.0f;
    red[tid] = e; __syncthreads();
    #pragma unroll
    for (int s = 256; s > 0; s >>= 1) {
        if (tid < s) red[tid] += red[tid + s];
        __syncthreads();
    }
    const float a = e / red[0];

    if (tid < Nn) {
        alpha_out[(size_t)b * Nn + tid] = a;
        sa[tid] = a;
    }
    __syncthreads();

    const float* eb = emb + (size_t)b * Nn * Hh;
    float acc = 0.0f;
    #pragma unroll 8
    for (int n = 0; n < Nn; n++)
        acc = fmaf(sa[n], eb[(size_t)n * Hh + tid], acc);
    resps[b * Hh + tid] = acc;
}

// ---------------------------------------------------------------------------
// Fast small 512x512x512 GEMM: 64x64 CTA tile, 4x4 microtile, 256 threads.
// out = act(A @ op(B) [+ Cadd])
// ---------------------------------------------------------------------------
template <bool TRANSB, bool DOADD, bool DOTANH>
__global__ __launch_bounds__(256)
void gemm512_fast(const float* __restrict__ A,
                  const float* __restrict__ B,
                  const float* __restrict__ Cadd,
                  float* __restrict__ out)
{
    __shared__ float As[16][68];   // [k][row]
    __shared__ float Bs[16][68];   // [k][col]
    const int tid = threadIdx.x;
    const int tx = tid & 15, ty = tid >> 4;
    const int col0 = blockIdx.x * 64, row0 = blockIdx.y * 64;

    float acc[4][4];
    #pragma unroll
    for (int i = 0; i < 4; i++)
        #pragma unroll
        for (int j = 0; j < 4; j++) acc[i][j] = 0.0f;

    for (int kt = 0; kt < 32; kt++) {
        const int k0 = kt * 16;
        // A: 64 rows x 16 k
        {
            const int r = tid >> 2, k4 = (tid & 3) * 4;
            const float4 v = *(const float4*)&A[(size_t)(row0 + r) * Hh + k0 + k4];
            As[k4 + 0][r] = v.x; As[k4 + 1][r] = v.y;
            As[k4 + 2][r] = v.z; As[k4 + 3][r] = v.w;
        }
        // B: 16 k x 64 cols
        if (TRANSB) {
            const int c = tid >> 2, k4 = (tid & 3) * 4;
            const float4 v = *(const float4*)&B[(size_t)(col0 + c) * Hh + k0 + k4];
            Bs[k4 + 0][c] = v.x; Bs[k4 + 1][c] = v.y;
            Bs[k4 + 2][c] = v.z; Bs[k4 + 3][c] = v.w;
        } else {
            const int k = tid >> 4, c4 = (tid & 15) * 4;
            const float4 v = *(const float4*)&B[(size_t)(k0 + k) * Hh + col0 + c4];
            *(float4*)&Bs[k][c4] = v;
        }
        __syncthreads();

        #pragma unroll
        for (int k = 0; k < 16; k++) {
            float a[4], bb[4];
            #pragma unroll
            for (int i = 0; i < 4; i++) a[i]  = As[k][ty * 4 + i];
            #pragma unroll
            for (int j = 0; j < 4; j++) bb[j] = Bs[k][tx * 4 + j];
            #pragma unroll
            for (int i = 0; i < 4; i++)
                #pragma unroll
                for (int j = 0; j < 4; j++)
                    acc[i][j] = fmaf(a[i], bb[j], acc[i][j]);
        }
        __syncthreads();
    }

    #pragma unroll
    for (int i = 0; i < 4; i++) {
        #pragma unroll
        for (int j = 0; j < 4; j++) {
            const size_t idx = (size_t)(row0 + ty * 4 + i) * Hh + col0 + tx * 4 + j;
            float v = acc[i][j];
            if (DOADD) v += Cadd[idx];
            if (DOTANH) v = tanhf(v);
            out[idx] = v;
        }
    }
}

// ---------------------------------------------------------------------------
extern "C" void kernel_launch(void* const* d_in, const int* in_sizes, int n_in,
                              void* d_out, int out_size)
{
    const float* spk  = (const float*)d_in[0];
    const float* mask = (const float*)d_in[1];
    const float* tr   = (const float*)d_in[2];
    const float* Ws   = (const float*)d_in[3];
    const float* Wr   = (const float*)d_in[4];
    const float* w    = (const float*)d_in[5];
    const float* Wp   = (const float*)d_in[6];
    const float* Wx   = (const float*)d_in[7];

    float* out = (float*)d_out;
    float* resp_out  = out;
    float* alpha_out = out + Bsz * Hh;

    float *pWresp, *prx, *pspart, *presps;
    __nv_bfloat16 *pAhi, *pAlo, *pBhi, *pBlo;
    cudaGetSymbolAddress((void**)&pWresp, g_Wresp);
    cudaGetSymbolAddress((void**)&prx, g_rx);
    cudaGetSymbolAddress((void**)&pspart, g_scores_part);
    cudaGetSymbolAddress((void**)&presps, g_resps);
    cudaGetSymbolAddress((void**)&pAhi, g_Ahi);
    cudaGetSymbolAddress((void**)&pAlo, g_Alo);
    cudaGetSymbolAddress((void**)&pBhi, g_Bhi);
    cudaGetSymbolAddress((void**)&pBlo, g_Blo);

    static bool attr_set = false;
    if (!attr_set) {
        cudaFuncSetAttribute(score_mma,
                             cudaFuncAttributeMaxDynamicSharedMemorySize,
                             SM_BYTES);
        attr_set = true;
    }

    // pre-split planes
    split_spk<<<(Bsz * Nn * Hh / 2) / 256, 256>>>(spk, pAhi, pAlo);
    split_ws<<<Hh / 2, Hh>>>(Ws, pBhi, pBlo);
    // W_resp = true_resp @ W_r ; rx = true_resp @ Wx^T
    gemm512_fast<false, false, false><<<dim3(8, 8), 256>>>(tr, Wr, nullptr, pWresp);
    gemm512_fast<true, false, false><<<dim3(8, 8), 256>>>(tr, Wx, nullptr, prx);
    // score partials (3xBF16 tensor cores, ldmatrix)
    score_mma<<<dim3(1024, 4), 256, SM_BYTES>>>(pAhi, pAlo, pBhi, pBlo,
                                                pWresp, w, pspart);
    // softmax + weighted sum
    softmax_weight_kernel<<<Bsz, 512>>>(pspart, mask, spk, alpha_out, presps);
    // out = tanh(resps @ Wp^T + rx)
    gemm512_fast<true, true, true><<<dim3(8, 8), 256>>>(presps, Wp, prx, resp_out);
}